// round 1
// baseline (speedup 1.0000x reference)
#include <cuda_runtime.h>

#define BATCH  8
#define SEQ    2048
#define DMODEL 512
#define NHEAD  8
#define DHEAD  64
#define ROWS   (BATCH * SEQ)     // 16384
#define QKVDIM (3 * DMODEL)      // 1536

// Scratch (allocation-free contract: __device__ globals)
__device__ float g_xn [ROWS * DMODEL];   // 32 MB
__device__ float g_qkv[ROWS * QKVDIM];   // 96 MB
__device__ float g_att[ROWS * DMODEL];   // 32 MB

// ---------------------------------------------------------------------------
// LayerNorm: one block (128 threads) per row of 512
// ---------------------------------------------------------------------------
__global__ __launch_bounds__(128) void ln_kernel(
    const float* __restrict__ x, const float* __restrict__ gamma,
    const float* __restrict__ beta, float* __restrict__ out)
{
    int row = blockIdx.x;
    int t   = threadIdx.x;
    const float* xr = x + (size_t)row * DMODEL;
    float4 v = *(const float4*)(xr + t * 4);
    float s  = v.x + v.y + v.z + v.w;
    float ss = v.x * v.x + v.y * v.y + v.z * v.z + v.w * v.w;
#pragma unroll
    for (int m = 16; m; m >>= 1) {
        s  += __shfl_xor_sync(0xffffffffu, s,  m);
        ss += __shfl_xor_sync(0xffffffffu, ss, m);
    }
    __shared__ float red[8];
    if ((t & 31) == 0) { red[t >> 5] = s; red[4 + (t >> 5)] = ss; }
    __syncthreads();
    float tot  = red[0] + red[1] + red[2] + red[3];
    float tot2 = red[4] + red[5] + red[6] + red[7];
    float mu   = tot * (1.0f / DMODEL);
    float var  = tot2 * (1.0f / DMODEL) - mu * mu;
    float rstd = rsqrtf(var + 1e-6f);
    float4 g = *(const float4*)(gamma + t * 4);
    float4 b = *(const float4*)(beta  + t * 4);
    float4 o;
    o.x = (v.x - mu) * rstd * g.x + b.x;
    o.y = (v.y - mu) * rstd * g.y + b.y;
    o.z = (v.z - mu) * rstd * g.z + b.z;
    o.w = (v.w - mu) * rstd * g.w + b.w;
    *(float4*)(out + (size_t)row * DMODEL + t * 4) = o;
}

// ---------------------------------------------------------------------------
// SGEMM (NT): C[M,N] = A[M,K] * B[N,K]^T (+ bias[n]); 128x128x8 tiles,
// 256 threads, 8x8 micro-tile, transposed smem tiles, reg-staged prefetch.
// M, N, K all multiples of 128/128/8 here; no bounds checks needed.
// ---------------------------------------------------------------------------
template <bool BIAS>
__global__ __launch_bounds__(256) void sgemm_nt(
    const float* __restrict__ A, const float* __restrict__ Bw,
    const float* __restrict__ bias, float* __restrict__ C,
    int N, int K)
{
    __shared__ float As[8][128];
    __shared__ float Bs[8][128];
    int t  = threadIdx.x;
    int m0 = blockIdx.y * 128, n0 = blockIdx.x * 128;
    int lr = t & 127;            // tile row for loads
    int lk = (t >> 7) << 2;      // 0 or 4: k sub-offset
    const float* Ag = A  + (size_t)(m0 + lr) * K + lk;
    const float* Bg = Bw + (size_t)(n0 + lr) * K + lk;
    int tx = t & 15, ty = t >> 4;

    float acc[8][8];
#pragma unroll
    for (int i = 0; i < 8; i++)
#pragma unroll
        for (int j = 0; j < 8; j++) acc[i][j] = 0.f;

    float4 ra = *(const float4*)Ag;
    float4 rb = *(const float4*)Bg;
    int kt_n = K >> 3;
    for (int kt = 0; kt < kt_n; kt++) {
        As[lk + 0][lr] = ra.x; As[lk + 1][lr] = ra.y;
        As[lk + 2][lr] = ra.z; As[lk + 3][lr] = ra.w;
        Bs[lk + 0][lr] = rb.x; Bs[lk + 1][lr] = rb.y;
        Bs[lk + 2][lr] = rb.z; Bs[lk + 3][lr] = rb.w;
        __syncthreads();
        if (kt + 1 < kt_n) {
            ra = *(const float4*)(Ag + (size_t)(kt + 1) * 8);
            rb = *(const float4*)(Bg + (size_t)(kt + 1) * 8);
        }
#pragma unroll
        for (int k = 0; k < 8; k++) {
            float4 a0 = *(const float4*)&As[k][ty * 4];
            float4 a1 = *(const float4*)&As[k][ty * 4 + 64];
            float4 b0 = *(const float4*)&Bs[k][tx * 4];
            float4 b1 = *(const float4*)&Bs[k][tx * 4 + 64];
            float av[8] = {a0.x, a0.y, a0.z, a0.w, a1.x, a1.y, a1.z, a1.w};
            float bv[8] = {b0.x, b0.y, b0.z, b0.w, b1.x, b1.y, b1.z, b1.w};
#pragma unroll
            for (int i = 0; i < 8; i++)
#pragma unroll
                for (int j = 0; j < 8; j++)
                    acc[i][j] = fmaf(av[i], bv[j], acc[i][j]);
        }
        __syncthreads();
    }

#pragma unroll
    for (int i = 0; i < 8; i++) {
        int m = m0 + ty * 4 + (i & 3) + ((i >> 2) << 6);
        float4 o0 = make_float4(acc[i][0], acc[i][1], acc[i][2], acc[i][3]);
        float4 o1 = make_float4(acc[i][4], acc[i][5], acc[i][6], acc[i][7]);
        if (BIAS) {
            float4 c0 = *(const float4*)(bias + n0 + tx * 4);
            float4 c1 = *(const float4*)(bias + n0 + tx * 4 + 64);
            o0.x += c0.x; o0.y += c0.y; o0.z += c0.z; o0.w += c0.w;
            o1.x += c1.x; o1.y += c1.y; o1.z += c1.z; o1.w += c1.w;
        }
        *(float4*)(C + (size_t)m * N + n0 + tx * 4)      = o0;
        *(float4*)(C + (size_t)m * N + n0 + tx * 4 + 64) = o1;
    }
}

// ---------------------------------------------------------------------------
// Flash attention (fp32, online softmax).
// Block = 128 Q rows of one (b,h); 256 threads (16 tx over keys/d, 16 ty over
// rows); loop over 64-key chunks. smem: Qs[d][m], Ks[d][key], Vs[key][d],
// Ps[m][key] (ld 68 to kill bank conflicts). ~100KB dynamic smem, 1 CTA/SM.
// ---------------------------------------------------------------------------
#define ATTN_SMEM_FLOATS (64 * 128 + 64 * 64 + 64 * 64 + 128 * 68)

__global__ __launch_bounds__(256, 1) void attn_kernel(
    const float* __restrict__ qkv, float* __restrict__ out)
{
    extern __shared__ float smembuf[];
    float* Qs = smembuf;            // [64][128]  (d-major)
    float* Ks = Qs + 64 * 128;      // [64][64]   (d-major)
    float* Vs = Ks + 64 * 64;       // [64][64]   (key-major)
    float* Ps = Vs + 64 * 64;       // [128][68]  (m-major, padded)
    const int PLD = 68;

    int t  = threadIdx.x;
    int tx = t & 15, ty = t >> 4;
    int bh = blockIdx.y;
    int b  = bh >> 3, h = bh & 7;
    int mbase = blockIdx.x * 128;
    size_t seq0 = (size_t)b * SEQ;
    const float scale = 0.125f;     // 1/sqrt(64)

    // Q tile -> Qs[d][m], pre-scaled
    {
        int row = t & 127;
        int d40 = t >> 7;
        const float* qp = qkv + (seq0 + mbase + row) * QKVDIM + h * DHEAD;
#pragma unroll
        for (int j = 0; j < 8; j++) {
            int d4 = d40 + 2 * j;
            float4 q = *(const float4*)(qp + d4 * 4);
            Qs[(d4 * 4 + 0) * 128 + row] = q.x * scale;
            Qs[(d4 * 4 + 1) * 128 + row] = q.y * scale;
            Qs[(d4 * 4 + 2) * 128 + row] = q.z * scale;
            Qs[(d4 * 4 + 3) * 128 + row] = q.w * scale;
        }
    }

    float o[8][4];
    float Mr[8], Lr[8];
#pragma unroll
    for (int r = 0; r < 8; r++) {
        Mr[r] = -1e30f; Lr[r] = 0.f;
#pragma unroll
        for (int c = 0; c < 4; c++) o[r][c] = 0.f;
    }

    int krow  = t & 63;
    int kd40  = t >> 6;   // 0..3
    int vrow0 = t >> 4;   // 0..15
    int vd4   = t & 15;

    for (int kc = 0; kc < SEQ / 64; kc++) {
        __syncthreads();   // prev PV done before overwriting Ks/Vs; Qs ready

        // K chunk -> Ks[d][key] (transpose on store)
        {
            const float* kp = qkv + (seq0 + kc * 64 + krow) * QKVDIM + DMODEL + h * DHEAD;
#pragma unroll
            for (int j = 0; j < 4; j++) {
                int d4 = kd40 + 4 * j;
                float4 kq = *(const float4*)(kp + d4 * 4);
                Ks[(d4 * 4 + 0) * 64 + krow] = kq.x;
                Ks[(d4 * 4 + 1) * 64 + krow] = kq.y;
                Ks[(d4 * 4 + 2) * 64 + krow] = kq.z;
                Ks[(d4 * 4 + 3) * 64 + krow] = kq.w;
            }
            // V chunk -> Vs[key][d] (natural)
#pragma unroll
            for (int j = 0; j < 4; j++) {
                int vr = vrow0 + 16 * j;
                const float* vp = qkv + (seq0 + kc * 64 + vr) * QKVDIM
                                  + 2 * DMODEL + h * DHEAD + vd4 * 4;
                *(float4*)&Vs[vr * 64 + vd4 * 4] = *(const float4*)vp;
            }
        }
        __syncthreads();

        // S = (Q*scale) K^T : micro 8 rows x 4 keys per thread
        float s[8][4];
#pragma unroll
        for (int r = 0; r < 8; r++)
#pragma unroll
            for (int c = 0; c < 4; c++) s[r][c] = 0.f;

#pragma unroll 8
        for (int d = 0; d < 64; d++) {
            float4 a0 = *(const float4*)&Qs[d * 128 + ty * 4];
            float4 a1 = *(const float4*)&Qs[d * 128 + ty * 4 + 64];
            float4 bk = *(const float4*)&Ks[d * 64 + tx * 4];
            float av[8] = {a0.x, a0.y, a0.z, a0.w, a1.x, a1.y, a1.z, a1.w};
            float bv[4] = {bk.x, bk.y, bk.z, bk.w};
#pragma unroll
            for (int r = 0; r < 8; r++)
#pragma unroll
                for (int c = 0; c < 4; c++)
                    s[r][c] = fmaf(av[r], bv[c], s[r][c]);
        }

        // Online softmax (row groups = 16 consecutive lanes)
#pragma unroll
        for (int r = 0; r < 8; r++) {
            float cm = fmaxf(fmaxf(s[r][0], s[r][1]), fmaxf(s[r][2], s[r][3]));
#pragma unroll
            for (int m = 8; m; m >>= 1)
                cm = fmaxf(cm, __shfl_xor_sync(0xffffffffu, cm, m));
            float nm = fmaxf(Mr[r], cm);
            float al = __expf(Mr[r] - nm);
            float rs = 0.f;
#pragma unroll
            for (int c = 0; c < 4; c++) {
                float p = __expf(s[r][c] - nm);
                s[r][c] = p; rs += p;
            }
#pragma unroll
            for (int m = 8; m; m >>= 1)
                rs += __shfl_xor_sync(0xffffffffu, rs, m);
            Lr[r] = Lr[r] * al + rs;
            Mr[r] = nm;
#pragma unroll
            for (int c = 0; c < 4; c++) o[r][c] *= al;
            int ml = ty * 4 + (r & 3) + ((r >> 2) << 6);
            *(float4*)&Ps[ml * PLD + tx * 4] =
                make_float4(s[r][0], s[r][1], s[r][2], s[r][3]);
        }
        __syncthreads();

        // O += P @ V : micro 8 rows x 4 d-cols, 4 keys per step
#pragma unroll 4
        for (int k4 = 0; k4 < 16; k4++) {
            float4 v0 = *(const float4*)&Vs[(k4 * 4 + 0) * 64 + tx * 4];
            float4 v1 = *(const float4*)&Vs[(k4 * 4 + 1) * 64 + tx * 4];
            float4 v2 = *(const float4*)&Vs[(k4 * 4 + 2) * 64 + tx * 4];
            float4 v3 = *(const float4*)&Vs[(k4 * 4 + 3) * 64 + tx * 4];
#pragma unroll
            for (int r = 0; r < 8; r++) {
                int ml = ty * 4 + (r & 3) + ((r >> 2) << 6);
                float4 av = *(const float4*)&Ps[ml * PLD + k4 * 4];
                o[r][0] = fmaf(av.x, v0.x, o[r][0]);
                o[r][0] = fmaf(av.y, v1.x, o[r][0]);
                o[r][0] = fmaf(av.z, v2.x, o[r][0]);
                o[r][0] = fmaf(av.w, v3.x, o[r][0]);
                o[r][1] = fmaf(av.x, v0.y, o[r][1]);
                o[r][1] = fmaf(av.y, v1.y, o[r][1]);
                o[r][1] = fmaf(av.z, v2.y, o[r][1]);
                o[r][1] = fmaf(av.w, v3.y, o[r][1]);
                o[r][2] = fmaf(av.x, v0.z, o[r][2]);
                o[r][2] = fmaf(av.y, v1.z, o[r][2]);
                o[r][2] = fmaf(av.z, v2.z, o[r][2]);
                o[r][2] = fmaf(av.w, v3.z, o[r][2]);
                o[r][3] = fmaf(av.x, v0.w, o[r][3]);
                o[r][3] = fmaf(av.y, v1.w, o[r][3]);
                o[r][3] = fmaf(av.z, v2.w, o[r][3]);
                o[r][3] = fmaf(av.w, v3.w, o[r][3]);
            }
        }
    }

    // Normalize and write [b, n, h*64 + d]
#pragma unroll
    for (int r = 0; r < 8; r++) {
        int ml = ty * 4 + (r & 3) + ((r >> 2) << 6);
        float inv = 1.0f / Lr[r];
        float4 ov = make_float4(o[r][0] * inv, o[r][1] * inv,
                                o[r][2] * inv, o[r][3] * inv);
        *(float4*)(out + (seq0 + mbase + ml) * DMODEL + h * DHEAD + tx * 4) = ov;
    }
}

// ---------------------------------------------------------------------------
extern "C" void kernel_launch(void* const* d_in, const int* in_sizes, int n_in,
                              void* d_out, int out_size)
{
    (void)in_sizes; (void)n_in; (void)out_size;
    const float* x      = (const float*)d_in[0];
    const float* w_qkv  = (const float*)d_in[1];
    const float* w_proj = (const float*)d_in[2];
    const float* b_proj = (const float*)d_in[3];
    const float* gamma  = (const float*)d_in[4];
    const float* beta   = (const float*)d_in[5];
    float* out = (float*)d_out;

    float *xn, *qkvp, *att;
    cudaGetSymbolAddress((void**)&xn,   g_xn);
    cudaGetSymbolAddress((void**)&qkvp, g_qkv);
    cudaGetSymbolAddress((void**)&att,  g_att);

    const int SMEM = ATTN_SMEM_FLOATS * (int)sizeof(float);
    cudaFuncSetAttribute(attn_kernel,
                         cudaFuncAttributeMaxDynamicSharedMemorySize, SMEM);

    ln_kernel<<<ROWS, 128>>>(x, gamma, beta, xn);
    sgemm_nt<false><<<dim3(QKVDIM / 128, ROWS / 128), 256>>>(
        xn, w_qkv, nullptr, qkvp, QKVDIM, DMODEL);
    attn_kernel<<<dim3(SEQ / 128, BATCH * NHEAD), 256, SMEM>>>(qkvp, att);
    sgemm_nt<true><<<dim3(DMODEL / 128, ROWS / 128), 256>>>(
        att, w_proj, b_proj, out, DMODEL, DMODEL);
}

// round 2
// speedup vs baseline: 2.3562x; 2.3562x over previous
#include <cuda_runtime.h>
#include <cstdint>

#define BATCH  8
#define SEQ    2048
#define DMODEL 512
#define NHEAD  8
#define DHEAD  64
#define ROWS   (BATCH * SEQ)     // 16384
#define QKVDIM (3 * DMODEL)      // 1536

// Scratch (allocation-free contract: __device__ globals)
__device__ float g_xn [ROWS * DMODEL];   // 32 MB
__device__ float g_qkv[ROWS * QKVDIM];   // 96 MB
__device__ float g_att[ROWS * DMODEL];   // 32 MB

// ---------------------------------------------------------------------------
// helpers: tf32 convert + m16n8k8 tf32 mma
// ---------------------------------------------------------------------------
__device__ __forceinline__ uint32_t f2tf(float x) {
    uint32_t r;
    asm("cvt.rna.tf32.f32 %0, %1;" : "=r"(r) : "f"(x));
    return r;
}

__device__ __forceinline__ void mma8(float& c0, float& c1, float& c2, float& c3,
                                     uint32_t a0, uint32_t a1, uint32_t a2, uint32_t a3,
                                     uint32_t b0, uint32_t b1) {
    asm volatile(
        "mma.sync.aligned.m16n8k8.row.col.f32.tf32.tf32.f32 "
        "{%0,%1,%2,%3}, {%4,%5,%6,%7}, {%8,%9}, {%0,%1,%2,%3};"
        : "+f"(c0), "+f"(c1), "+f"(c2), "+f"(c3)
        : "r"(a0), "r"(a1), "r"(a2), "r"(a3), "r"(b0), "r"(b1));
}

// ---------------------------------------------------------------------------
// LayerNorm: one block (128 threads) per row of 512
// ---------------------------------------------------------------------------
__global__ __launch_bounds__(128) void ln_kernel(
    const float* __restrict__ x, const float* __restrict__ gamma,
    const float* __restrict__ beta, float* __restrict__ out)
{
    int row = blockIdx.x;
    int t   = threadIdx.x;
    const float* xr = x + (size_t)row * DMODEL;
    float4 v = *(const float4*)(xr + t * 4);
    float s  = v.x + v.y + v.z + v.w;
    float ss = v.x * v.x + v.y * v.y + v.z * v.z + v.w * v.w;
#pragma unroll
    for (int m = 16; m; m >>= 1) {
        s  += __shfl_xor_sync(0xffffffffu, s,  m);
        ss += __shfl_xor_sync(0xffffffffu, ss, m);
    }
    __shared__ float red[8];
    if ((t & 31) == 0) { red[t >> 5] = s; red[4 + (t >> 5)] = ss; }
    __syncthreads();
    float tot  = red[0] + red[1] + red[2] + red[3];
    float tot2 = red[4] + red[5] + red[6] + red[7];
    float mu   = tot * (1.0f / DMODEL);
    float var  = tot2 * (1.0f / DMODEL) - mu * mu;
    float rstd = rsqrtf(var + 1e-6f);
    float4 g = *(const float4*)(gamma + t * 4);
    float4 b = *(const float4*)(beta  + t * 4);
    float4 o;
    o.x = (v.x - mu) * rstd * g.x + b.x;
    o.y = (v.y - mu) * rstd * g.y + b.y;
    o.z = (v.z - mu) * rstd * g.z + b.z;
    o.w = (v.w - mu) * rstd * g.w + b.w;
    *(float4*)(out + (size_t)row * DMODEL + t * 4) = o;
}

// ---------------------------------------------------------------------------
// tf32 tensor-core GEMM (NT): C[M,N] = A[M,K=512] * B[N,K=512]^T (+bias)
// CTA tile 128x128x16, 8 warps (2m x 4n), warp tile 64x32 (4x4 mma tiles).
// Smem raw fp32 with padded stride 20 (conflict-free fragment LDS),
// cvt->tf32 after LDS.
// ---------------------------------------------------------------------------
#define GK 512
#define GS 20   // smem row stride (floats)

template <bool BIAS>
__global__ __launch_bounds__(256, 2) void mm_tf32(
    const float* __restrict__ A, const float* __restrict__ Bw,
    const float* __restrict__ bias, float* __restrict__ C, int N)
{
    __shared__ float As[128][GS];
    __shared__ float Bs[128][GS];
    int t    = threadIdx.x;
    int m0   = blockIdx.y * 128, n0 = blockIdx.x * 128;
    int warp = t >> 5, lane = t & 31, g = lane >> 2, tq = lane & 3;
    int wm   = (warp >> 2) * 64, wn = (warp & 3) * 32;

    int lrow = t >> 2;        // 0..63 (and +64)
    int lk4  = t & 3;         // float4 within 16-k tile
    const float* Ag = A  + (size_t)(m0 + lrow) * GK + lk4 * 4;
    const float* Bg = Bw + (size_t)(n0 + lrow) * GK + lk4 * 4;

    float acc[4][4][4];
#pragma unroll
    for (int i = 0; i < 4; i++)
#pragma unroll
        for (int j = 0; j < 4; j++)
#pragma unroll
            for (int r = 0; r < 4; r++) acc[i][j][r] = 0.f;

    float4 ra0 = *(const float4*)Ag;
    float4 ra1 = *(const float4*)(Ag + (size_t)64 * GK);
    float4 rb0 = *(const float4*)Bg;
    float4 rb1 = *(const float4*)(Bg + (size_t)64 * GK);

    const int NT = GK / 16;
    for (int kt = 0; kt < NT; kt++) {
        *(float4*)&As[lrow][lk4 * 4]      = ra0;
        *(float4*)&As[lrow + 64][lk4 * 4] = ra1;
        *(float4*)&Bs[lrow][lk4 * 4]      = rb0;
        *(float4*)&Bs[lrow + 64][lk4 * 4] = rb1;
        __syncthreads();
        if (kt + 1 < NT) {
            ra0 = *(const float4*)(Ag + (kt + 1) * 16);
            ra1 = *(const float4*)(Ag + (size_t)64 * GK + (kt + 1) * 16);
            rb0 = *(const float4*)(Bg + (kt + 1) * 16);
            rb1 = *(const float4*)(Bg + (size_t)64 * GK + (kt + 1) * 16);
        }
#pragma unroll
        for (int ks = 0; ks < 2; ks++) {
            int k0 = ks * 8;
            uint32_t af[4][4], bf[4][2];
#pragma unroll
            for (int mt = 0; mt < 4; mt++) {
                int r = wm + mt * 16 + g;
                af[mt][0] = f2tf(As[r][k0 + tq]);
                af[mt][1] = f2tf(As[r + 8][k0 + tq]);
                af[mt][2] = f2tf(As[r][k0 + tq + 4]);
                af[mt][3] = f2tf(As[r + 8][k0 + tq + 4]);
            }
#pragma unroll
            for (int nt = 0; nt < 4; nt++) {
                int r = wn + nt * 8 + g;
                bf[nt][0] = f2tf(Bs[r][k0 + tq]);
                bf[nt][1] = f2tf(Bs[r][k0 + tq + 4]);
            }
#pragma unroll
            for (int mt = 0; mt < 4; mt++)
#pragma unroll
                for (int nt = 0; nt < 4; nt++)
                    mma8(acc[mt][nt][0], acc[mt][nt][1], acc[mt][nt][2], acc[mt][nt][3],
                         af[mt][0], af[mt][1], af[mt][2], af[mt][3],
                         bf[nt][0], bf[nt][1]);
        }
        __syncthreads();
    }

#pragma unroll
    for (int mt = 0; mt < 4; mt++) {
#pragma unroll
        for (int nt = 0; nt < 4; nt++) {
            int row = m0 + wm + mt * 16 + g;
            int col = n0 + wn + nt * 8 + 2 * tq;
            float b0 = 0.f, b1 = 0.f;
            if (BIAS) { b0 = bias[col]; b1 = bias[col + 1]; }
            float2 v0 = make_float2(acc[mt][nt][0] + b0, acc[mt][nt][1] + b1);
            float2 v1 = make_float2(acc[mt][nt][2] + b0, acc[mt][nt][3] + b1);
            *(float2*)(C + (size_t)row * N + col)       = v0;
            *(float2*)(C + (size_t)(row + 8) * N + col) = v1;
        }
    }
}

// ---------------------------------------------------------------------------
// Flash attention, tf32 tensor cores.
// CTA = 128 Q rows of one (b,h); 8 warps, warp owns 16 rows.
// Q fragments live in registers for the whole kernel. 64-key chunks.
// Smem: QP[128][68] (Q staging, then per-warp P slabs), Ks[64][68], Vs[64][68].
// ---------------------------------------------------------------------------
#define AS 68   // attn smem stride (floats)
#define ATTN_SMEM_FLOATS (128 * AS + 64 * AS + 64 * AS)

__global__ __launch_bounds__(256, 1) void attn_tf32(
    const float* __restrict__ qkv, float* __restrict__ out)
{
    extern __shared__ float sm[];
    float* QP = sm;                  // [128][AS]
    float* Ks = sm + 128 * AS;       // [64][AS]
    float* Vs = Ks + 64 * AS;        // [64][AS]

    int t = threadIdx.x, warp = t >> 5, lane = t & 31, g = lane >> 2, tq = lane & 3;
    int bh = blockIdx.y, b = bh >> 3, h = bh & 7;
    int mb = blockIdx.x * 128;
    size_t seq0 = (size_t)b * SEQ;
    const float* base  = qkv + seq0 * QKVDIM + h * DHEAD;
    const float* kbase = base + DMODEL;
    const float* vbase = base + 2 * DMODEL;

    // Stage Q tile (coalesced), then build per-warp Q fragments (scaled).
    {
        int d4 = t & 15, r0 = t >> 4;
#pragma unroll
        for (int j = 0; j < 8; j++) {
            int row = r0 + 16 * j;
            *(float4*)&QP[row * AS + d4 * 4] =
                *(const float4*)(base + (size_t)(mb + row) * QKVDIM + d4 * 4);
        }
    }
    __syncthreads();

    uint32_t qf[8][4];
    float* Pw = QP + warp * 16 * AS;   // warp-private 16-row slab
    {
        const float scale = 0.125f;    // 1/sqrt(64)
#pragma unroll
        for (int ks = 0; ks < 8; ks++) {
            qf[ks][0] = f2tf(Pw[g * AS + ks * 8 + tq] * scale);
            qf[ks][1] = f2tf(Pw[(g + 8) * AS + ks * 8 + tq] * scale);
            qf[ks][2] = f2tf(Pw[g * AS + ks * 8 + tq + 4] * scale);
            qf[ks][3] = f2tf(Pw[(g + 8) * AS + ks * 8 + tq + 4] * scale);
        }
    }
    // Each warp only read its own slab; no cross-warp hazard before P writes.

    float oacc[8][4];
#pragma unroll
    for (int nt = 0; nt < 8; nt++)
#pragma unroll
        for (int r = 0; r < 4; r++) oacc[nt][r] = 0.f;
    float M0 = -1e30f, M1 = -1e30f, L0 = 0.f, L1 = 0.f;

    for (int kc = 0; kc < SEQ / 64; kc++) {
        __syncthreads();   // previous PV reads of Ks/Vs complete
        {
            int d4 = t & 15, r0 = t >> 4;
#pragma unroll
            for (int j = 0; j < 4; j++) {
                int row = r0 + 16 * j;
                size_t key = (size_t)(kc * 64 + row);
                *(float4*)&Ks[row * AS + d4 * 4] =
                    *(const float4*)(kbase + key * QKVDIM + d4 * 4);
                *(float4*)&Vs[row * AS + d4 * 4] =
                    *(const float4*)(vbase + key * QKVDIM + d4 * 4);
            }
        }
        __syncthreads();

        // S = (Q*scale) K^T : 8 n-tiles (64 keys)
        float sacc[8][4];
#pragma unroll
        for (int nt = 0; nt < 8; nt++)
#pragma unroll
            for (int r = 0; r < 4; r++) sacc[nt][r] = 0.f;

#pragma unroll
        for (int ks = 0; ks < 8; ks++) {
            int k0 = ks * 8;
#pragma unroll
            for (int nt = 0; nt < 8; nt++) {
                int kr = nt * 8 + g;
                uint32_t b0 = f2tf(Ks[kr * AS + k0 + tq]);
                uint32_t b1 = f2tf(Ks[kr * AS + k0 + tq + 4]);
                mma8(sacc[nt][0], sacc[nt][1], sacc[nt][2], sacc[nt][3],
                     qf[ks][0], qf[ks][1], qf[ks][2], qf[ks][3], b0, b1);
            }
        }

        // Online softmax. Thread owns rows g (c0,c1) and g+8 (c2,c3),
        // cols {nt*8+2tq, +1}; full row = 4 lanes (xor 1,2).
        float cm0 = sacc[0][0], cm1 = sacc[0][2];
#pragma unroll
        for (int nt = 0; nt < 8; nt++) {
            cm0 = fmaxf(cm0, fmaxf(sacc[nt][0], sacc[nt][1]));
            cm1 = fmaxf(cm1, fmaxf(sacc[nt][2], sacc[nt][3]));
        }
        cm0 = fmaxf(cm0, __shfl_xor_sync(0xffffffffu, cm0, 1));
        cm0 = fmaxf(cm0, __shfl_xor_sync(0xffffffffu, cm0, 2));
        cm1 = fmaxf(cm1, __shfl_xor_sync(0xffffffffu, cm1, 1));
        cm1 = fmaxf(cm1, __shfl_xor_sync(0xffffffffu, cm1, 2));
        float nM0 = fmaxf(M0, cm0), nM1 = fmaxf(M1, cm1);
        float a0 = __expf(M0 - nM0), a1 = __expf(M1 - nM1);
        float rs0 = 0.f, rs1 = 0.f;
#pragma unroll
        for (int nt = 0; nt < 8; nt++) {
            sacc[nt][0] = __expf(sacc[nt][0] - nM0);
            sacc[nt][1] = __expf(sacc[nt][1] - nM0);
            sacc[nt][2] = __expf(sacc[nt][2] - nM1);
            sacc[nt][3] = __expf(sacc[nt][3] - nM1);
            rs0 += sacc[nt][0] + sacc[nt][1];
            rs1 += sacc[nt][2] + sacc[nt][3];
        }
        rs0 += __shfl_xor_sync(0xffffffffu, rs0, 1);
        rs0 += __shfl_xor_sync(0xffffffffu, rs0, 2);
        rs1 += __shfl_xor_sync(0xffffffffu, rs1, 1);
        rs1 += __shfl_xor_sync(0xffffffffu, rs1, 2);
        L0 = L0 * a0 + rs0;  M0 = nM0;
        L1 = L1 * a1 + rs1;  M1 = nM1;

        // Rescale O, park P in the warp-private smem slab (C-layout),
        // reload as A-fragments for PV.
#pragma unroll
        for (int nt = 0; nt < 8; nt++) {
            oacc[nt][0] *= a0; oacc[nt][1] *= a0;
            oacc[nt][2] *= a1; oacc[nt][3] *= a1;
            *(float2*)&Pw[g * AS + nt * 8 + 2 * tq] =
                make_float2(sacc[nt][0], sacc[nt][1]);
            *(float2*)&Pw[(g + 8) * AS + nt * 8 + 2 * tq] =
                make_float2(sacc[nt][2], sacc[nt][3]);
        }
        __syncwarp();

        // O += P @ V
#pragma unroll
        for (int ks = 0; ks < 8; ks++) {
            int k0 = ks * 8;
            uint32_t pa0 = f2tf(Pw[g * AS + k0 + tq]);
            uint32_t pa1 = f2tf(Pw[(g + 8) * AS + k0 + tq]);
            uint32_t pa2 = f2tf(Pw[g * AS + k0 + tq + 4]);
            uint32_t pa3 = f2tf(Pw[(g + 8) * AS + k0 + tq + 4]);
#pragma unroll
            for (int nt = 0; nt < 8; nt++) {
                uint32_t b0 = f2tf(Vs[(k0 + tq) * AS + nt * 8 + g]);
                uint32_t b1 = f2tf(Vs[(k0 + tq + 4) * AS + nt * 8 + g]);
                mma8(oacc[nt][0], oacc[nt][1], oacc[nt][2], oacc[nt][3],
                     pa0, pa1, pa2, pa3, b0, b1);
            }
        }
    }

    // Normalize, write out[b, n, h*64 + d]
    float i0 = 1.0f / L0, i1 = 1.0f / L1;
    int row0 = mb + warp * 16 + g;
#pragma unroll
    for (int nt = 0; nt < 8; nt++) {
        int col = h * DHEAD + nt * 8 + 2 * tq;
        *(float2*)(out + (seq0 + row0) * DMODEL + col) =
            make_float2(oacc[nt][0] * i0, oacc[nt][1] * i0);
        *(float2*)(out + (seq0 + row0 + 8) * DMODEL + col) =
            make_float2(oacc[nt][2] * i1, oacc[nt][3] * i1);
    }
}

// ---------------------------------------------------------------------------
extern "C" void kernel_launch(void* const* d_in, const int* in_sizes, int n_in,
                              void* d_out, int out_size)
{
    (void)in_sizes; (void)n_in; (void)out_size;
    const float* x      = (const float*)d_in[0];
    const float* w_qkv  = (const float*)d_in[1];
    const float* w_proj = (const float*)d_in[2];
    const float* b_proj = (const float*)d_in[3];
    const float* gamma  = (const float*)d_in[4];
    const float* beta   = (const float*)d_in[5];
    float* out = (float*)d_out;

    float *xn, *qkvp, *att;
    cudaGetSymbolAddress((void**)&xn,   g_xn);
    cudaGetSymbolAddress((void**)&qkvp, g_qkv);
    cudaGetSymbolAddress((void**)&att,  g_att);

    const int SMEM = ATTN_SMEM_FLOATS * (int)sizeof(float);
    cudaFuncSetAttribute(attn_tf32,
                         cudaFuncAttributeMaxDynamicSharedMemorySize, SMEM);

    ln_kernel<<<ROWS, 128>>>(x, gamma, beta, xn);
    mm_tf32<false><<<dim3(QKVDIM / 128, ROWS / 128), 256>>>(
        xn, w_qkv, nullptr, qkvp, QKVDIM);
    attn_tf32<<<dim3(SEQ / 128, BATCH * NHEAD), 256, SMEM>>>(qkvp, att);
    mm_tf32<true><<<dim3(DMODEL / 128, ROWS / 128), 256>>>(
        att, w_proj, b_proj, out, DMODEL);
}